// round 15
// baseline (speedup 1.0000x reference)
#include <cuda_runtime.h>
#include <cuda_fp16.h>
#include <math.h>
#include <stdint.h>

#define NN 8192
#define D 128
#define WORDS (NN/32)
#define MT 64
#define CK 128
#define PITCH 136
#define ATT_SMEM ((MT + CK) * PITCH * 2)   // 52224 bytes
#define KP 40

__device__ unsigned int g_bits[NN*WORDS];
__device__ __half g_Vt16[2*(size_t)D*NN];
__device__ float g_f1[2*NN];
__device__ float g_f2[2*NN];
__device__ float g_m[2*NN];
__device__ float g_f1o[NN];
__device__ float g_f2o[NN];
__device__ float g_mo[NN];
__device__ float g_num[2*(size_t)NN*D];
__device__ float g_l[2*NN];
__device__ float g_part[D];
__device__ __half g_x16[2*(size_t)NN*D];
__device__ __half g_h16[2*(size_t)NN*256];
__device__ __half g_comb16[2*(size_t)NN*256];
__device__ __half g_mlp116[2*(size_t)NN*256];
__device__ __half g_wh16[2*2*D*D];
__device__ __half g_wo16[2*256*D];
__device__ __half g_w116[2*256*256];
__device__ __half g_w216[2*256*D];
__device__ float g_cval[3*32];
__device__ int   g_cidx[3*32];

__device__ __forceinline__ uint32_t smem_u32(const void* p) {
    uint32_t a;
    asm("{ .reg .u64 t; cvta.to.shared.u64 t, %1; cvt.u32.u64 %0, t; }"
        : "=r"(a) : "l"(p));
    return a;
}
__device__ __forceinline__ void ldsm4(uint32_t& r0, uint32_t& r1, uint32_t& r2,
                                      uint32_t& r3, uint32_t addr) {
    asm volatile("ldmatrix.sync.aligned.m8n8.x4.shared.b16 {%0,%1,%2,%3}, [%4];"
                 : "=r"(r0), "=r"(r1), "=r"(r2), "=r"(r3) : "r"(addr));
}
__device__ __forceinline__ void mma16816(float* c, const uint32_t* a,
                                         uint32_t b0, uint32_t b1) {
    asm volatile(
        "mma.sync.aligned.m16n8k16.row.col.f32.f16.f16.f32 "
        "{%0,%1,%2,%3},{%4,%5,%6,%7},{%8,%9},{%0,%1,%2,%3};"
        : "+f"(c[0]), "+f"(c[1]), "+f"(c[2]), "+f"(c[3])
        : "r"(a[0]), "r"(a[1]), "r"(a[2]), "r"(a[3]), "r"(b0), "r"(b1));
}

// ---------------- pack adjacency (int4 vectorized) ----------------
__global__ void pack_kernel(const int4* __restrict__ adj4,
                            unsigned int* __restrict__ bits) {
    unsigned int g = blockIdx.x * 256 + threadIdx.x;
    int4 v = adj4[g];
    unsigned int nib = (unsigned)(v.x != 0) | ((unsigned)(v.y != 0) << 1)
                     | ((unsigned)(v.z != 0) << 2) | ((unsigned)(v.w != 0) << 3);
    unsigned int word = nib << ((threadIdx.x & 7) * 4);
    word |= __shfl_xor_sync(0xffffffffu, word, 1);
    word |= __shfl_xor_sync(0xffffffffu, word, 2);
    word |= __shfl_xor_sync(0xffffffffu, word, 4);
    if ((g & 7u) == 0u) bits[g >> 3] = word;
}

// ---------------- merged prep: splits, transposed weight planes, zero fills ----------------
// task layout (gridDim.x per task chosen at launch):
//   z=0: split x -> x16 (hi/lo), 1024 blocks
//   z=1: x -> comb16 left half (hi/lo), 1024 blocks
//   z=2: wprep W_heads head0 (4x4=16 blocks used, bx = kb*4+nb)
//   z=3: wprep W_heads head1
//   z=4: wprep W_out (8x4=32 blocks)
//   z=5: wprep ge_w1 (8x8=64 blocks)
//   z=6: wprep ge_w2 (8x4=32 blocks)
//   z=7: zero f1/f2/f1o/f2o/part (1 block x 256: strided)
__global__ void prep_kernel(const float* __restrict__ x,
                            const float* __restrict__ W_heads,
                            const float* __restrict__ W_out,
                            const float* __restrict__ ge_w1,
                            const float* __restrict__ ge_w2,
                            __half* __restrict__ x16,
                            __half* __restrict__ comb16,
                            __half* __restrict__ wh16,
                            __half* __restrict__ wo16,
                            __half* __restrict__ w116,
                            __half* __restrict__ w216,
                            float* __restrict__ f1, float* __restrict__ f2,
                            float* __restrict__ f1o, float* __restrict__ f2o,
                            float* __restrict__ part) {
    int task = blockIdx.z;
    int tid = threadIdx.x;
    if (task == 0 || task == 1) {
        int idx = blockIdx.x * 256 + tid;     // over NN*32 float4
        if (idx >= NN * D / 4) return;
        float4 v = ((const float4*)x)[idx];
        __half h[4], l[4];
        h[0] = __float2half_rn(v.x); l[0] = __float2half_rn(v.x - __half2float(h[0]));
        h[1] = __float2half_rn(v.y); l[1] = __float2half_rn(v.y - __half2float(h[1]));
        h[2] = __float2half_rn(v.z); l[2] = __float2half_rn(v.z - __half2float(h[2]));
        h[3] = __float2half_rn(v.w); l[3] = __float2half_rn(v.w - __half2float(h[3]));
        if (task == 0) {
            size_t o = (size_t)idx * 4;
            *(uint2*)(x16 + o) = *(uint2*)h;
            *(uint2*)(x16 + (size_t)NN * D + o) = *(uint2*)l;
        } else {
            int row = idx >> 5, c = idx & 31;
            size_t o = (size_t)row * 256 + c * 4;
            *(uint2*)(comb16 + o) = *(uint2*)h;
            *(uint2*)(comb16 + (size_t)NN * 256 + o) = *(uint2*)l;
        }
        return;
    }
    if (task == 7) {
        for (int i = tid; i < 2 * NN; i += 256) { f1[i] = 0.f; f2[i] = 0.f; }
        for (int i = tid; i < NN; i += 256) { f1o[i] = 0.f; f2o[i] = 0.f; }
        if (tid < D) part[tid] = 0.f;
        return;
    }
    // wprep tasks: [K][N] fp32 -> [N][K] fp16 hi/lo, 32x32 tiles
    const float* in; __half* out; int N, K; size_t plane;
    int nbt;   // tiles along n
    if (task == 2) { in = W_heads;        out = wh16;              N = D;  K = D;  plane = D * D;    nbt = 4; }
    else if (task == 3) { in = W_heads + D * D; out = wh16 + 2 * D * D; N = D; K = D; plane = D * D; nbt = 4; }
    else if (task == 4) { in = W_out;     out = wo16;  N = D;   K = 256; plane = (size_t)256 * D;   nbt = 4; }
    else if (task == 5) { in = ge_w1;     out = w116;  N = 256; K = 256; plane = (size_t)256 * 256; nbt = 8; }
    else                { in = ge_w2;     out = w216;  N = D;   K = 256; plane = (size_t)256 * D;   nbt = 4; }
    int kbt = blockIdx.x / nbt, nb = (blockIdx.x % nbt) * 32;
    int kb = kbt * 32;
    if (kb >= K) return;
    __shared__ float t[32][33];
    int tx = tid & 31, ty = tid >> 5;
#pragma unroll
    for (int r = 0; r < 32; r += 8)
        t[ty + r][tx] = in[(size_t)(kb + ty + r) * N + nb + tx];
    __syncthreads();
#pragma unroll
    for (int r = 0; r < 32; r += 8) {
        float v = t[tx][ty + r];
        __half h = __float2half_rn(v);
        out[(size_t)(nb + ty + r) * K + kb + tx] = h;
        out[plane + (size_t)(nb + ty + r) * K + kb + tx] =
            __float2half_rn(v - __half2float(h));
    }
}

// hi/lo fp16 HMMA GEMM with fused epilogues (round-13 proven).
__global__ __launch_bounds__(256) void hgemm16_kernel(
    const __half* __restrict__ A, size_t aPlane, size_t aZ,
    const __half* __restrict__ Bt, size_t bPlane, size_t bZ,
    const float* __restrict__ bias,
    void* __restrict__ Cv, int ldc, size_t cZ,
    int K, int act, int outmode, size_t oPlane,
    const float* __restrict__ avec, float* __restrict__ f1out,
    float* __restrict__ f2out) {
    __shared__ __half As[2][128][KP];
    __shared__ __half Bs[2][64][KP];

    int tid = threadIdx.x;
    int lane = tid & 31, warp = tid >> 5;
    int wm = warp & 3, wn = warp >> 2;
    const __half* Az = A + blockIdx.z * aZ + (size_t)(blockIdx.x * 128) * K;
    const __half* Btz = Bt + blockIdx.z * bZ;
    int n0 = blockIdx.y * 64;

    uint32_t sbA = smem_u32(&As[0][0][0]);
    uint32_t sbB = smem_u32(&Bs[0][0][0]);
    int g = lane >> 3, wl = lane & 7;
    uint32_t aoff = (uint32_t)((wm * 32 + (g & 1) * 8 + wl) * (KP * 2) + (g >> 1) * 16);
    uint32_t boff = (uint32_t)((wn * 32 + (g >> 1) * 8 + wl) * (KP * 2) + (g & 1) * 16);

    float acc[2][4][4];
#pragma unroll
    for (int mt = 0; mt < 2; mt++)
#pragma unroll
        for (int nt = 0; nt < 4; nt++)
#pragma unroll
            for (int c = 0; c < 4; c++) acc[mt][nt][c] = 0.f;

    int arow = tid >> 1, aks = (tid & 1) * 16;
    int bn = tid >> 2, bks = (tid & 3) * 8;

    for (int kb = 0; kb < K; kb += 32) {
        const __half* ag = Az + (size_t)arow * K + kb + aks;
        *(uint4*)&As[0][arow][aks]     = *(const uint4*)ag;
        *(uint4*)&As[0][arow][aks + 8] = *(const uint4*)(ag + 8);
        *(uint4*)&As[1][arow][aks]     = *(const uint4*)(ag + aPlane);
        *(uint4*)&As[1][arow][aks + 8] = *(const uint4*)(ag + aPlane + 8);
        const __half* bg = Btz + (size_t)(n0 + bn) * K + kb + bks;
        *(uint4*)&Bs[0][bn][bks] = *(const uint4*)bg;
        *(uint4*)&Bs[1][bn][bks] = *(const uint4*)(bg + bPlane);
        __syncthreads();

#pragma unroll
        for (int ks = 0; ks < 2; ks++) {
            uint32_t ah[2][4], al[2][4], bh[2][4], bl[2][4];
#pragma unroll
            for (int mt = 0; mt < 2; mt++) {
                uint32_t ra = aoff + mt * (16 * KP * 2) + ks * 32;
                ldsm4(ah[mt][0], ah[mt][1], ah[mt][2], ah[mt][3], sbA + ra);
                ldsm4(al[mt][0], al[mt][1], al[mt][2], al[mt][3], sbA + 128 * KP * 2 + ra);
            }
#pragma unroll
            for (int ng = 0; ng < 2; ng++) {
                uint32_t rb = boff + ng * (16 * KP * 2) + ks * 32;
                ldsm4(bh[ng][0], bh[ng][1], bh[ng][2], bh[ng][3], sbB + rb);
                ldsm4(bl[ng][0], bl[ng][1], bl[ng][2], bl[ng][3], sbB + 64 * KP * 2 + rb);
            }
#pragma unroll
            for (int mt = 0; mt < 2; mt++)
#pragma unroll
                for (int ng = 0; ng < 2; ng++) {
                    mma16816(acc[mt][2*ng],   ah[mt], bh[ng][0], bh[ng][1]);
                    mma16816(acc[mt][2*ng+1], ah[mt], bh[ng][2], bh[ng][3]);
                    mma16816(acc[mt][2*ng],   ah[mt], bl[ng][0], bl[ng][1]);
                    mma16816(acc[mt][2*ng+1], ah[mt], bl[ng][2], bl[ng][3]);
                    mma16816(acc[mt][2*ng],   al[mt], bh[ng][0], bh[ng][1]);
                    mma16816(acc[mt][2*ng+1], al[mt], bh[ng][2], bh[ng][3]);
                }
        }
        __syncthreads();
    }

    const float* avecz = avec ? avec + blockIdx.z * 256 : nullptr;
    float* f1z = f1out + blockIdx.z * NN;
    float* f2z = f2out + blockIdx.z * NN;
    __half* ts = &As[0][0][0];
    float csum[4][2];
#pragma unroll
    for (int nt = 0; nt < 4; nt++) { csum[nt][0] = 0.f; csum[nt][1] = 0.f; }

#pragma unroll
    for (int mt = 0; mt < 2; mt++) {
        int r0 = wm * 32 + mt * 16 + (lane >> 2);
        float s1 = 0.f, s2 = 0.f, t1 = 0.f, t2 = 0.f;
#pragma unroll
        for (int nt = 0; nt < 4; nt++) {
            int col = n0 + wn * 32 + nt * 8 + (lane & 3) * 2;
            float b0 = 0.f, b1 = 0.f;
            if (bias) { b0 = bias[col]; b1 = bias[col + 1]; }
            float o00 = acc[mt][nt][0] + b0, o01 = acc[mt][nt][1] + b1;
            float o10 = acc[mt][nt][2] + b0, o11 = acc[mt][nt][3] + b1;
            if (avecz) {
                float a0 = __ldg(avecz + col), a1 = __ldg(avecz + col + 1);
                float c0 = __ldg(avecz + 128 + col), c1 = __ldg(avecz + 128 + col + 1);
                s1 += o00 * a0 + o01 * a1;
                s2 += o00 * c0 + o01 * c1;
                t1 += o10 * a0 + o11 * a1;
                t2 += o10 * c0 + o11 * c1;
            }
            if (act == 1) {
                o00 = fmaxf(o00, 0.f); o01 = fmaxf(o01, 0.f);
                o10 = fmaxf(o10, 0.f); o11 = fmaxf(o11, 0.f);
            }
            if (outmode == 0) {
                float* Cz = (float*)Cv + blockIdx.z * cZ + (size_t)(blockIdx.x * 128) * ldc;
                *(float2*)(Cz + (size_t)r0 * ldc + col) = make_float2(o00, o01);
                *(float2*)(Cz + (size_t)(r0 + 8) * ldc + col) = make_float2(o10, o11);
            } else if (outmode == 1) {
                __half* Cz = (__half*)Cv + (size_t)(blockIdx.x * 128) * ldc;
                __half h0 = __float2half_rn(o00), h1 = __float2half_rn(o01);
                __half h2 = __float2half_rn(o10), h3 = __float2half_rn(o11);
                __half2 hi0; hi0.x = h0; hi0.y = h1;
                __half2 hi1; hi1.x = h2; hi1.y = h3;
                __half2 lo0; lo0.x = __float2half_rn(o00 - __half2float(h0));
                             lo0.y = __float2half_rn(o01 - __half2float(h1));
                __half2 lo1; lo1.x = __float2half_rn(o10 - __half2float(h2));
                             lo1.y = __float2half_rn(o11 - __half2float(h3));
                *(__half2*)(Cz + (size_t)r0 * ldc + col) = hi0;
                *(__half2*)(Cz + (size_t)(r0 + 8) * ldc + col) = hi1;
                *(__half2*)(Cz + oPlane + (size_t)r0 * ldc + col) = lo0;
                *(__half2*)(Cz + oPlane + (size_t)(r0 + 8) * ldc + col) = lo1;
            } else if (outmode == 2) {
                int lc = wn * 32 + nt * 8 + (lane & 3) * 2;
                ts[lc * 136 + r0] = __float2half_rn(o00);
                ts[(lc + 1) * 136 + r0] = __float2half_rn(o01);
                ts[lc * 136 + r0 + 8] = __float2half_rn(o10);
                ts[(lc + 1) * 136 + r0 + 8] = __float2half_rn(o11);
            } else {
                csum[nt][0] += o00 + o10;
                csum[nt][1] += o01 + o11;
            }
        }
        if (avecz) {
            s1 += __shfl_xor_sync(0xffffffffu, s1, 1);
            s1 += __shfl_xor_sync(0xffffffffu, s1, 2);
            s2 += __shfl_xor_sync(0xffffffffu, s2, 1);
            s2 += __shfl_xor_sync(0xffffffffu, s2, 2);
            t1 += __shfl_xor_sync(0xffffffffu, t1, 1);
            t1 += __shfl_xor_sync(0xffffffffu, t1, 2);
            t2 += __shfl_xor_sync(0xffffffffu, t2, 1);
            t2 += __shfl_xor_sync(0xffffffffu, t2, 2);
            if ((lane & 3) == 0) {
                int gr = blockIdx.x * 128 + r0;
                atomicAdd(f1z + gr, s1);
                atomicAdd(f2z + gr, s2);
                atomicAdd(f1z + gr + 8, t1);
                atomicAdd(f2z + gr + 8, t2);
            }
        }
    }

    if (outmode == 2) {
        __syncthreads();
        __half* Vz = (__half*)Cv + blockIdx.z * cZ;
        int c = tid >> 2, chb = (tid & 3) * 32;
        const __half* src = ts + c * 136 + chb;
        __half* dst = Vz + (size_t)(n0 + c) * NN + blockIdx.x * 128 + chb;
#pragma unroll
        for (int k = 0; k < 4; k++)
            *(uint4*)(dst + k * 8) = *(const uint4*)(src + k * 8);
    } else if (outmode == 3) {
#pragma unroll
        for (int nt = 0; nt < 4; nt++) {
#pragma unroll
            for (int v = 0; v < 2; v++) {
                float s = csum[nt][v];
                s += __shfl_xor_sync(0xffffffffu, s, 4);
                s += __shfl_xor_sync(0xffffffffu, s, 8);
                s += __shfl_xor_sync(0xffffffffu, s, 16);
                if ((lane >> 2) == 0) {
                    int col = n0 + wn * 32 + nt * 8 + (lane & 3) * 2 + v;
                    atomicAdd((float*)Cv + col, s);
                }
            }
        }
    }
}

__global__ void topk_kernel(const float* __restrict__ f2b,
                            float* __restrict__ cval, int* __restrict__ cidx) {
    __shared__ float sv[NN];
    __shared__ unsigned long long red[8];
    int head = blockIdx.x;
    int tid = threadIdx.x, lane = tid & 31, warp = tid >> 5;
    const float* f2 = f2b + (size_t)head * NN;
#pragma unroll
    for (int k = 0; k < NN / 256; k++) sv[tid + k * 256] = f2[tid + k * 256];
    __syncthreads();
    for (int t = 0; t < 32; t++) {
        unsigned long long best = 0;
#pragma unroll
        for (int k = 0; k < NN / 256; k++) {
            int j = tid + k * 256;
            unsigned int u = __float_as_uint(sv[j]);
            u = (u & 0x80000000u) ? ~u : (u | 0x80000000u);
            unsigned long long pk = ((unsigned long long)u << 32) | (unsigned)j;
            best = best > pk ? best : pk;
        }
#pragma unroll
        for (int o = 16; o > 0; o >>= 1) {
            unsigned long long other = __shfl_xor_sync(0xffffffffu, best, o);
            best = best > other ? best : other;
        }
        if (lane == 0) red[warp] = best;
        __syncthreads();
        if (tid == 0) {
            unsigned long long m = red[0];
#pragma unroll
            for (int w = 1; w < 8; w++) m = m > red[w] ? m : red[w];
            int idx = (int)(m & 0xffffffffu);
            cval[head * 32 + t] = sv[idx];
            cidx[head * 32 + t] = idx;
            sv[idx] = -INFINITY;
        }
        __syncthreads();
    }
}

__global__ void rowmax_fast(const unsigned int* __restrict__ bits,
                            const float* __restrict__ f1b,
                            const float* __restrict__ f2b,
                            const float* __restrict__ cval,
                            const int* __restrict__ cidx,
                            float* __restrict__ mb) {
    int head = blockIdx.y;
    int i = blockIdx.x * 256 + threadIdx.x;
    __shared__ float scv[32];
    __shared__ int sci[32];
    if (threadIdx.x < 32) {
        scv[threadIdx.x] = cval[head * 32 + threadIdx.x];
        sci[threadIdx.x] = cidx[head * 32 + threadIdx.x];
    }
    __syncthreads();
    const unsigned int* rb = bits + (size_t)i * WORDS;
    float mx = 0.f;
    bool found = false;
    for (int c = 0; c < 32; c++) {
        int j = sci[c];
        if ((rb[j >> 5] >> (j & 31)) & 1u) { mx = scv[c]; found = true; break; }
    }
    if (!found) {
        const float* f2 = f2b + (size_t)head * NN;
        mx = -INFINITY;
        for (int w = 0; w < WORDS; w++) {
            unsigned int b = rb[w];
            while (b) {
                int bit = __ffs(b) - 1; b &= b - 1;
                mx = fmaxf(mx, f2[w * 32 + bit]);
            }
        }
    }
    float v = f1b[(size_t)head * NN + i] + mx;
    mb[(size_t)head * NN + i] = v > 0.f ? v : 0.2f * v;
}

// single-buffer fp32-accum attention (round-13 proven)
__global__ __launch_bounds__(256) void att_hmma(
    const unsigned int* __restrict__ bits,
    const float* __restrict__ f1b, const float* __restrict__ f2b,
    const float* __restrict__ mb,
    const __half* __restrict__ Vt,
    int mode, __half* __restrict__ outH, size_t hPlane,
    float* __restrict__ numF, float* __restrict__ lout) {
    extern __shared__ __half dsm[];
    __half* Ps = dsm;
    __half* Vs = dsm + MT * PITCH;
    __shared__ float sm_l[MT];

    int head = blockIdx.y;
    int split = blockIdx.z;
    int jbase = mode ? split * (NN / 2) : 0;
    int nch = mode ? (NN / 2) / CK : NN / CK;
    const float* f1 = f1b + (size_t)head * NN;
    const float* f2 = f2b + (size_t)head * NN;
    const float* mrv = mb + (size_t)head * NN;
    int i0 = blockIdx.x * MT;

    int tid = threadIdx.x;
    int lane = tid & 31, warp = tid >> 5;
    uint32_t sb = smem_u32(dsm);

    int r = tid >> 2, q = tid & 3;
    float f1r = f1[i0 + r];
    float mr = mrv[i0 + r];
    __half2* prow = (__half2*)(Ps + r * PITCH + q * 32);

    int vn = tid >> 1, vp = tid & 1;
    const __half* vrow = Vt + (size_t)head * D * NN + (size_t)vn * NN + jbase + vp * 64;
    __half* vsrow = Vs + vn * PITCH + vp * 64;

    int mrow0 = (warp >> 1) * 16, ncol0 = (warp & 1) * 64;
    int g = lane >> 3, wl = lane & 7;
    uint32_t aaddr = sb + (mrow0 + wl + (g & 1) * 8) * (PITCH * 2) + (g >> 1) * 16;
    uint32_t baddr = sb + MT * (PITCH * 2)
                   + (ncol0 + wl + (g >> 1) * 8) * (PITCH * 2) + (g & 1) * 16;

    float acc[8][4];
#pragma unroll
    for (int nt = 0; nt < 8; nt++)
#pragma unroll
        for (int c = 0; c < 4; c++) acc[nt][c] = 0.f;
    float lsum = 0.f;

    for (int ch = 0; ch < nch; ch++) {
        int j0 = ch * CK;
        const uint4* vg = (const uint4*)(vrow + j0);
#pragma unroll
        for (int i = 0; i < 8; i++) {
            int ii = (i + 4 * vp) & 7;
            *(uint4*)(vsrow + ii * 8) = vg[ii];
        }

        unsigned int w = bits[(size_t)(i0 + r) * WORDS + ((jbase + j0) >> 5) + q];
        const float* f2c = f2 + jbase + j0 + q * 32;
#pragma unroll
        for (int s = 0; s < 16; s++) {
            int u = (s + 5 * q) & 15;
            float2 ff = *(const float2*)(f2c + 2 * u);
            float e0 = f1r + ff.x;
            float e1 = f1r + ff.y;
            e0 = fmaxf(e0, 0.2f * e0) - mr;
            e1 = fmaxf(e1, 0.2f * e1) - mr;
            float p0 = ((w >> (2 * u)) & 1u) ? __expf(e0) : 0.f;
            float p1 = ((w >> (2 * u + 1)) & 1u) ? __expf(e1) : 0.f;
            lsum += p0 + p1;
            prow[u] = __floats2half2_rn(p0, p1);
        }
        __syncthreads();

#pragma unroll
        for (int k = 0; k < 8; k++) {
            uint32_t a[4];
            ldsm4(a[0], a[1], a[2], a[3], aaddr + k * 32);
#pragma unroll
            for (int ng = 0; ng < 4; ng++) {
                uint32_t b[4];
                ldsm4(b[0], b[1], b[2], b[3], baddr + ng * (16 * PITCH * 2) + k * 32);
                mma16816(acc[2 * ng], a, b[0], b[1]);
                mma16816(acc[2 * ng + 1], a, b[2], b[3]);
            }
        }
        __syncthreads();
    }

    lsum += __shfl_xor_sync(0xffffffffu, lsum, 1);
    lsum += __shfl_xor_sync(0xffffffffu, lsum, 2);

    if (mode) {
        if (q == 0) lout[(size_t)split * NN + i0 + r] = lsum;
        float* nrow = numF + ((size_t)split * NN + i0) * D;
        int r0 = mrow0 + (lane >> 2);
#pragma unroll
        for (int nt = 0; nt < 8; nt++) {
            int col = ncol0 + nt * 8 + (lane & 3) * 2;
            *(float2*)(nrow + (size_t)r0 * D + col) = make_float2(acc[nt][0], acc[nt][1]);
            *(float2*)(nrow + (size_t)(r0 + 8) * D + col) = make_float2(acc[nt][2], acc[nt][3]);
        }
        return;
    }

    if (q == 0) sm_l[r] = lsum;
    __syncthreads();

    int r0 = mrow0 + (lane >> 2);
    float inv0 = 1.f / sm_l[r0];
    float inv1 = 1.f / sm_l[r0 + 8];
    int offH = head * 128;
#pragma unroll
    for (int nt = 0; nt < 8; nt++) {
        int col = ncol0 + nt * 8 + (lane & 3) * 2;
        float o00 = acc[nt][0] * inv0, o01 = acc[nt][1] * inv0;
        float o10 = acc[nt][2] * inv1, o11 = acc[nt][3] * inv1;
        o00 = o00 > 0.f ? o00 : expm1f(o00);
        o01 = o01 > 0.f ? o01 : expm1f(o01);
        o10 = o10 > 0.f ? o10 : expm1f(o10);
        o11 = o11 > 0.f ? o11 : expm1f(o11);
        __half h0 = __float2half_rn(o00), h1 = __float2half_rn(o01);
        __half h2 = __float2half_rn(o10), h3 = __float2half_rn(o11);
        __half2 hi0; hi0.x = h0; hi0.y = h1;
        __half2 hi1; hi1.x = h2; hi1.y = h3;
        __half2 lo0; lo0.x = __float2half_rn(o00 - __half2float(h0));
                     lo0.y = __float2half_rn(o01 - __half2float(h1));
        __half2 lo1; lo1.x = __float2half_rn(o10 - __half2float(h2));
                     lo1.y = __float2half_rn(o11 - __half2float(h3));
        size_t b0 = (size_t)(i0 + r0) * 256 + offH + col;
        size_t b1 = (size_t)(i0 + r0 + 8) * 256 + offH + col;
        *(__half2*)(outH + b0) = hi0;
        *(__half2*)(outH + b1) = hi1;
        *(__half2*)(outH + hPlane + b0) = lo0;
        *(__half2*)(outH + hPlane + b1) = lo1;
    }
}

__global__ void combine2(const float* __restrict__ num, const float* __restrict__ lpart,
                         float* __restrict__ out, __half* __restrict__ comb16) {
    int i = blockIdx.x, t = threadIdx.x;
    float s = num[(size_t)i * D + t] + num[((size_t)NN + i) * D + t];
    float l = lpart[i] + lpart[NN + i];
    float o = s / l;
    o = o > 0.f ? o : expm1f(o);
    out[(size_t)i * D + t] = o;
    __half h = __float2half_rn(o);
    comb16[(size_t)i * 256 + 128 + t] = h;
    comb16[(size_t)NN * 256 + (size_t)i * 256 + 128 + t] =
        __float2half_rn(o - __half2float(h));
}

__global__ void mean_final(const float* __restrict__ part, float* __restrict__ out) {
    int t = threadIdx.x;
    out[t] = part[t] * (1.0f / (float)NN);
}

extern "C" void kernel_launch(void* const* d_in, const int* in_sizes, int n_in,
                              void* d_out, int out_size) {
    const int* adj = (const int*)d_in[0];
    const float* x = (const float*)d_in[1];
    const float* W_heads = (const float*)d_in[2];
    const float* a_heads = (const float*)d_in[3];
    const float* W_out = (const float*)d_in[4];
    const float* a_out = (const float*)d_in[5];
    const float* ge_w1 = (const float*)d_in[6];
    const float* ge_b1 = (const float*)d_in[7];
    const float* ge_w2 = (const float*)d_in[8];
    const float* ge_b2 = (const float*)d_in[9];
    float* out = (float*)d_out;

    unsigned int* bits; cudaGetSymbolAddress((void**)&bits, g_bits);
    __half* Vt16; cudaGetSymbolAddress((void**)&Vt16, g_Vt16);
    float* f1;    cudaGetSymbolAddress((void**)&f1, g_f1);
    float* f2;    cudaGetSymbolAddress((void**)&f2, g_f2);
    float* m;     cudaGetSymbolAddress((void**)&m, g_m);
    float* f1o;   cudaGetSymbolAddress((void**)&f1o, g_f1o);
    float* f2o;   cudaGetSymbolAddress((void**)&f2o, g_f2o);
    float* mo;    cudaGetSymbolAddress((void**)&mo, g_mo);
    float* num;   cudaGetSymbolAddress((void**)&num, g_num);
    float* lpart; cudaGetSymbolAddress((void**)&lpart, g_l);
    float* part;  cudaGetSymbolAddress((void**)&part, g_part);
    __half* x16;    cudaGetSymbolAddress((void**)&x16, g_x16);
    __half* h16;    cudaGetSymbolAddress((void**)&h16, g_h16);
    __half* comb16; cudaGetSymbolAddress((void**)&comb16, g_comb16);
    __half* mlp116; cudaGetSymbolAddress((void**)&mlp116, g_mlp116);
    __half* wh16;   cudaGetSymbolAddress((void**)&wh16, g_wh16);
    __half* wo16;   cudaGetSymbolAddress((void**)&wo16, g_wo16);
    __half* w116;   cudaGetSymbolAddress((void**)&w116, g_w116);
    __half* w216;   cudaGetSymbolAddress((void**)&w216, g_w216);
    float* cval;  cudaGetSymbolAddress((void**)&cval, g_cval);
    int* cidx;    cudaGetSymbolAddress((void**)&cidx, g_cidx);

    cudaFuncSetAttribute(att_hmma, cudaFuncAttributeMaxDynamicSharedMemorySize, ATT_SMEM);

    // one merged prep launch: splits + weight planes + zero fills (8 tasks)
    prep_kernel<<<dim3(1024, 1, 8), 256>>>(
        x, W_heads, W_out, ge_w1, ge_w2,
        x16, comb16, wh16, wo16, w116, w216,
        f1, f2, f1o, f2o, part);
    pack_kernel<<<NN * NN / 4 / 256, 256>>>((const int4*)adj, bits);

    // Wh both heads -> Vt16 transposed, + fused f1/f2
    hgemm16_kernel<<<dim3(NN / 128, D / 64, 2), 256>>>(
        x16, (size_t)NN * D, 0, wh16, D * D, 2 * D * D, nullptr,
        Vt16, NN, (size_t)D * NN, D, 0, 2, 0, a_heads, f1, f2);

    topk_kernel<<<2, 256>>>(f2, cval, cidx);
    rowmax_fast<<<dim3(NN / 256, 2), 256>>>(bits, f1, f2, cval, cidx, m);

    att_hmma<<<dim3(NN / MT, 2, 1), 256, ATT_SMEM>>>(
        bits, f1, f2, m, Vt16, 0, h16, (size_t)NN * 256, nullptr, nullptr);

    hgemm16_kernel<<<dim3(NN / 128, D / 64, 1), 256>>>(
        h16, (size_t)NN * 256, 0, wo16, 256 * D, 0, nullptr,
        Vt16, NN, 0, 256, 0, 2, 0, a_out, f1o, f2o);
    topk_kernel<<<1, 256>>>(f2o, cval + 64, cidx + 64);
    rowmax_fast<<<dim3(NN / 256, 1), 256>>>(bits, f1o, f2o, cval + 64, cidx + 64, mo);
    att_hmma<<<dim3(NN / MT, 1, 2), 256, ATT_SMEM>>>(
        bits, f1o, f2o, mo, Vt16, 1, nullptr, 0, num, lpart);
    combine2<<<NN, 128>>>(num, lpart, out, comb16);

    hgemm16_kernel<<<dim3(NN / 128, 256 / 64, 1), 256>>>(
        comb16, (size_t)NN * 256, 0, w116, 256 * 256, 0, ge_b1,
        mlp116, 256, 0, 256, 1, 1, (size_t)NN * 256, nullptr, f1o, f2o);
    hgemm16_kernel<<<dim3(NN / 128, D / 64, 1), 256>>>(
        mlp116, (size_t)NN * 256, 0, w216, 256 * D, 0, ge_b2,
        part, D, 0, 256, 1, 3, 0, nullptr, f1o, f2o);
    mean_final<<<1, 128>>>(part, out + (size_t)NN * D);
}

// round 16
// speedup vs baseline: 1.0624x; 1.0624x over previous
#include <cuda_runtime.h>
#include <cuda_fp16.h>
#include <math.h>
#include <stdint.h>

#define NN 8192
#define D 128
#define WORDS (NN/32)
#define MT 64
#define CK 128
#define PITCH 136
#define ATT_SMEM ((MT + CK) * PITCH * 2)   // 52224 bytes
#define KP 40

__device__ unsigned int g_bits[NN*WORDS];
__device__ __half g_Vt16[2*(size_t)D*NN];
__device__ float g_f1[2*NN];
__device__ float g_f2[2*NN];
__device__ float g_m[2*NN];
__device__ float g_f1o[NN];
__device__ float g_f2o[NN];
__device__ float g_mo[NN];
__device__ float g_num[2*(size_t)NN*D];
__device__ float g_l[2*NN];
__device__ float g_part[D];
__device__ __half g_x16[2*(size_t)NN*D];
__device__ __half g_h16[2*(size_t)NN*256];
__device__ __half g_comb16[2*(size_t)NN*256];
__device__ __half g_mlp116[2*(size_t)NN*256];
__device__ __half g_wh16[2*2*D*D];
__device__ __half g_wo16[2*256*D];
__device__ __half g_w116[2*256*256];
__device__ __half g_w216[2*256*D];
__device__ float g_cval[3*32];
__device__ int   g_cidx[3*32];

__device__ __forceinline__ uint32_t smem_u32(const void* p) {
    uint32_t a;
    asm("{ .reg .u64 t; cvta.to.shared.u64 t, %1; cvt.u32.u64 %0, t; }"
        : "=r"(a) : "l"(p));
    return a;
}
__device__ __forceinline__ void ldsm4(uint32_t& r0, uint32_t& r1, uint32_t& r2,
                                      uint32_t& r3, uint32_t addr) {
    asm volatile("ldmatrix.sync.aligned.m8n8.x4.shared.b16 {%0,%1,%2,%3}, [%4];"
                 : "=r"(r0), "=r"(r1), "=r"(r2), "=r"(r3) : "r"(addr));
}
__device__ __forceinline__ void mma16816(float* c, const uint32_t* a,
                                         uint32_t b0, uint32_t b1) {
    asm volatile(
        "mma.sync.aligned.m16n8k16.row.col.f32.f16.f16.f32 "
        "{%0,%1,%2,%3},{%4,%5,%6,%7},{%8,%9},{%0,%1,%2,%3};"
        : "+f"(c[0]), "+f"(c[1]), "+f"(c[2]), "+f"(c[3])
        : "r"(a[0]), "r"(a[1]), "r"(a[2]), "r"(a[3]), "r"(b0), "r"(b1));
}

// ---------------- pack adjacency (int4 vectorized) ----------------
__global__ void pack_kernel(const int4* __restrict__ adj4,
                            unsigned int* __restrict__ bits) {
    unsigned int g = blockIdx.x * 256 + threadIdx.x;
    int4 v = adj4[g];
    unsigned int nib = (unsigned)(v.x != 0) | ((unsigned)(v.y != 0) << 1)
                     | ((unsigned)(v.z != 0) << 2) | ((unsigned)(v.w != 0) << 3);
    unsigned int word = nib << ((threadIdx.x & 7) * 4);
    word |= __shfl_xor_sync(0xffffffffu, word, 1);
    word |= __shfl_xor_sync(0xffffffffu, word, 2);
    word |= __shfl_xor_sync(0xffffffffu, word, 4);
    if ((g & 7u) == 0u) bits[g >> 3] = word;
}

__global__ void split_kernel(const float* __restrict__ in,
                             __half* __restrict__ out, size_t n) {
    size_t idx = (size_t)(blockIdx.x * 256 + threadIdx.x) * 4;
    float4 v = *(const float4*)(in + idx);
    __half h[4], l[4];
    h[0] = __float2half_rn(v.x); l[0] = __float2half_rn(v.x - __half2float(h[0]));
    h[1] = __float2half_rn(v.y); l[1] = __float2half_rn(v.y - __half2float(h[1]));
    h[2] = __float2half_rn(v.z); l[2] = __float2half_rn(v.z - __half2float(h[2]));
    h[3] = __float2half_rn(v.w); l[3] = __float2half_rn(v.w - __half2float(h[3]));
    *(uint2*)(out + idx) = *(uint2*)h;
    *(uint2*)(out + n + idx) = *(uint2*)l;
}

__global__ void xcomb_kernel(const float* __restrict__ x, __half* __restrict__ comb16) {
    int idx = blockIdx.x * 256 + threadIdx.x;
    int row = idx >> 5, c = idx & 31;
    float4 v = ((const float4*)x)[idx];
    __half h[4], l[4];
    h[0] = __float2half_rn(v.x); l[0] = __float2half_rn(v.x - __half2float(h[0]));
    h[1] = __float2half_rn(v.y); l[1] = __float2half_rn(v.y - __half2float(h[1]));
    h[2] = __float2half_rn(v.z); l[2] = __float2half_rn(v.z - __half2float(h[2]));
    h[3] = __float2half_rn(v.w); l[3] = __float2half_rn(v.w - __half2float(h[3]));
    size_t o = (size_t)row * 256 + c * 4;
    *(uint2*)(comb16 + o) = *(uint2*)h;
    *(uint2*)(comb16 + (size_t)NN * 256 + o) = *(uint2*)l;
}

__global__ void wprep_kernel(const float* __restrict__ in, int N, int K,
                             __half* __restrict__ out, size_t plane,
                             size_t inZ, size_t outZ) {
    __shared__ float t[32][33];
    const float* inz = in + blockIdx.z * inZ;
    __half* outz = out + blockIdx.z * outZ;
    int kb = blockIdx.x * 32, nb = blockIdx.y * 32;
    int tx = threadIdx.x & 31, ty = threadIdx.x >> 5;
#pragma unroll
    for (int r = 0; r < 32; r += 8)
        t[ty + r][tx] = inz[(size_t)(kb + ty + r) * N + nb + tx];
    __syncthreads();
#pragma unroll
    for (int r = 0; r < 32; r += 8) {
        float v = t[tx][ty + r];
        __half h = __float2half_rn(v);
        outz[(size_t)(nb + ty + r) * K + kb + tx] = h;
        outz[plane + (size_t)(nb + ty + r) * K + kb + tx] =
            __float2half_rn(v - __half2float(h));
    }
}

// hi/lo fp16 HMMA GEMM with fused epilogues (round-13 proven).
__global__ __launch_bounds__(256) void hgemm16_kernel(
    const __half* __restrict__ A, size_t aPlane, size_t aZ,
    const __half* __restrict__ Bt, size_t bPlane, size_t bZ,
    const float* __restrict__ bias,
    void* __restrict__ Cv, int ldc, size_t cZ,
    int K, int act, int outmode, size_t oPlane,
    const float* __restrict__ avec, float* __restrict__ f1out,
    float* __restrict__ f2out) {
    __shared__ __half As[2][128][KP];
    __shared__ __half Bs[2][64][KP];

    int tid = threadIdx.x;
    int lane = tid & 31, warp = tid >> 5;
    int wm = warp & 3, wn = warp >> 2;
    const __half* Az = A + blockIdx.z * aZ + (size_t)(blockIdx.x * 128) * K;
    const __half* Btz = Bt + blockIdx.z * bZ;
    int n0 = blockIdx.y * 64;

    uint32_t sbA = smem_u32(&As[0][0][0]);
    uint32_t sbB = smem_u32(&Bs[0][0][0]);
    int g = lane >> 3, wl = lane & 7;
    uint32_t aoff = (uint32_t)((wm * 32 + (g & 1) * 8 + wl) * (KP * 2) + (g >> 1) * 16);
    uint32_t boff = (uint32_t)((wn * 32 + (g >> 1) * 8 + wl) * (KP * 2) + (g & 1) * 16);

    float acc[2][4][4];
#pragma unroll
    for (int mt = 0; mt < 2; mt++)
#pragma unroll
        for (int nt = 0; nt < 4; nt++)
#pragma unroll
            for (int c = 0; c < 4; c++) acc[mt][nt][c] = 0.f;

    int arow = tid >> 1, aks = (tid & 1) * 16;
    int bn = tid >> 2, bks = (tid & 3) * 8;

    for (int kb = 0; kb < K; kb += 32) {
        const __half* ag = Az + (size_t)arow * K + kb + aks;
        *(uint4*)&As[0][arow][aks]     = *(const uint4*)ag;
        *(uint4*)&As[0][arow][aks + 8] = *(const uint4*)(ag + 8);
        *(uint4*)&As[1][arow][aks]     = *(const uint4*)(ag + aPlane);
        *(uint4*)&As[1][arow][aks + 8] = *(const uint4*)(ag + aPlane + 8);
        const __half* bg = Btz + (size_t)(n0 + bn) * K + kb + bks;
        *(uint4*)&Bs[0][bn][bks] = *(const uint4*)bg;
        *(uint4*)&Bs[1][bn][bks] = *(const uint4*)(bg + bPlane);
        __syncthreads();

#pragma unroll
        for (int ks = 0; ks < 2; ks++) {
            uint32_t ah[2][4], al[2][4], bh[2][4], bl[2][4];
#pragma unroll
            for (int mt = 0; mt < 2; mt++) {
                uint32_t ra = aoff + mt * (16 * KP * 2) + ks * 32;
                ldsm4(ah[mt][0], ah[mt][1], ah[mt][2], ah[mt][3], sbA + ra);
                ldsm4(al[mt][0], al[mt][1], al[mt][2], al[mt][3], sbA + 128 * KP * 2 + ra);
            }
#pragma unroll
            for (int ng = 0; ng < 2; ng++) {
                uint32_t rb = boff + ng * (16 * KP * 2) + ks * 32;
                ldsm4(bh[ng][0], bh[ng][1], bh[ng][2], bh[ng][3], sbB + rb);
                ldsm4(bl[ng][0], bl[ng][1], bl[ng][2], bl[ng][3], sbB + 64 * KP * 2 + rb);
            }
#pragma unroll
            for (int mt = 0; mt < 2; mt++)
#pragma unroll
                for (int ng = 0; ng < 2; ng++) {
                    mma16816(acc[mt][2*ng],   ah[mt], bh[ng][0], bh[ng][1]);
                    mma16816(acc[mt][2*ng+1], ah[mt], bh[ng][2], bh[ng][3]);
                    mma16816(acc[mt][2*ng],   ah[mt], bl[ng][0], bl[ng][1]);
                    mma16816(acc[mt][2*ng+1], ah[mt], bl[ng][2], bl[ng][3]);
                    mma16816(acc[mt][2*ng],   al[mt], bh[ng][0], bh[ng][1]);
                    mma16816(acc[mt][2*ng+1], al[mt], bh[ng][2], bh[ng][3]);
                }
        }
        __syncthreads();
    }

    const float* avecz = avec ? avec + blockIdx.z * 256 : nullptr;
    float* f1z = f1out + blockIdx.z * NN;
    float* f2z = f2out + blockIdx.z * NN;
    __half* ts = &As[0][0][0];
    float csum[4][2];
#pragma unroll
    for (int nt = 0; nt < 4; nt++) { csum[nt][0] = 0.f; csum[nt][1] = 0.f; }

#pragma unroll
    for (int mt = 0; mt < 2; mt++) {
        int r0 = wm * 32 + mt * 16 + (lane >> 2);
        float s1 = 0.f, s2 = 0.f, t1 = 0.f, t2 = 0.f;
#pragma unroll
        for (int nt = 0; nt < 4; nt++) {
            int col = n0 + wn * 32 + nt * 8 + (lane & 3) * 2;
            float b0 = 0.f, b1 = 0.f;
            if (bias) { b0 = bias[col]; b1 = bias[col + 1]; }
            float o00 = acc[mt][nt][0] + b0, o01 = acc[mt][nt][1] + b1;
            float o10 = acc[mt][nt][2] + b0, o11 = acc[mt][nt][3] + b1;
            if (avecz) {
                float a0 = __ldg(avecz + col), a1 = __ldg(avecz + col + 1);
                float c0 = __ldg(avecz + 128 + col), c1 = __ldg(avecz + 128 + col + 1);
                s1 += o00 * a0 + o01 * a1;
                s2 += o00 * c0 + o01 * c1;
                t1 += o10 * a0 + o11 * a1;
                t2 += o10 * c0 + o11 * c1;
            }
            if (act == 1) {
                o00 = fmaxf(o00, 0.f); o01 = fmaxf(o01, 0.f);
                o10 = fmaxf(o10, 0.f); o11 = fmaxf(o11, 0.f);
            }
            if (outmode == 0) {
                float* Cz = (float*)Cv + blockIdx.z * cZ + (size_t)(blockIdx.x * 128) * ldc;
                *(float2*)(Cz + (size_t)r0 * ldc + col) = make_float2(o00, o01);
                *(float2*)(Cz + (size_t)(r0 + 8) * ldc + col) = make_float2(o10, o11);
            } else if (outmode == 1) {
                __half* Cz = (__half*)Cv + (size_t)(blockIdx.x * 128) * ldc;
                __half h0 = __float2half_rn(o00), h1 = __float2half_rn(o01);
                __half h2 = __float2half_rn(o10), h3 = __float2half_rn(o11);
                __half2 hi0; hi0.x = h0; hi0.y = h1;
                __half2 hi1; hi1.x = h2; hi1.y = h3;
                __half2 lo0; lo0.x = __float2half_rn(o00 - __half2float(h0));
                             lo0.y = __float2half_rn(o01 - __half2float(h1));
                __half2 lo1; lo1.x = __float2half_rn(o10 - __half2float(h2));
                             lo1.y = __float2half_rn(o11 - __half2float(h3));
                *(__half2*)(Cz + (size_t)r0 * ldc + col) = hi0;
                *(__half2*)(Cz + (size_t)(r0 + 8) * ldc + col) = hi1;
                *(__half2*)(Cz + oPlane + (size_t)r0 * ldc + col) = lo0;
                *(__half2*)(Cz + oPlane + (size_t)(r0 + 8) * ldc + col) = lo1;
            } else if (outmode == 2) {
                int lc = wn * 32 + nt * 8 + (lane & 3) * 2;
                ts[lc * 136 + r0] = __float2half_rn(o00);
                ts[(lc + 1) * 136 + r0] = __float2half_rn(o01);
                ts[lc * 136 + r0 + 8] = __float2half_rn(o10);
                ts[(lc + 1) * 136 + r0 + 8] = __float2half_rn(o11);
            } else {
                csum[nt][0] += o00 + o10;
                csum[nt][1] += o01 + o11;
            }
        }
        if (avecz) {
            s1 += __shfl_xor_sync(0xffffffffu, s1, 1);
            s1 += __shfl_xor_sync(0xffffffffu, s1, 2);
            s2 += __shfl_xor_sync(0xffffffffu, s2, 1);
            s2 += __shfl_xor_sync(0xffffffffu, s2, 2);
            t1 += __shfl_xor_sync(0xffffffffu, t1, 1);
            t1 += __shfl_xor_sync(0xffffffffu, t1, 2);
            t2 += __shfl_xor_sync(0xffffffffu, t2, 1);
            t2 += __shfl_xor_sync(0xffffffffu, t2, 2);
            if ((lane & 3) == 0) {
                int gr = blockIdx.x * 128 + r0;
                atomicAdd(f1z + gr, s1);
                atomicAdd(f2z + gr, s2);
                atomicAdd(f1z + gr + 8, t1);
                atomicAdd(f2z + gr + 8, t2);
            }
        }
    }

    if (outmode == 2) {
        __syncthreads();
        __half* Vz = (__half*)Cv + blockIdx.z * cZ;
        int c = tid >> 2, chb = (tid & 3) * 32;
        const __half* src = ts + c * 136 + chb;
        __half* dst = Vz + (size_t)(n0 + c) * NN + blockIdx.x * 128 + chb;
#pragma unroll
        for (int k = 0; k < 4; k++)
            *(uint4*)(dst + k * 8) = *(const uint4*)(src + k * 8);
    } else if (outmode == 3) {
#pragma unroll
        for (int nt = 0; nt < 4; nt++) {
#pragma unroll
            for (int v = 0; v < 2; v++) {
                float s = csum[nt][v];
                s += __shfl_xor_sync(0xffffffffu, s, 4);
                s += __shfl_xor_sync(0xffffffffu, s, 8);
                s += __shfl_xor_sync(0xffffffffu, s, 16);
                if ((lane >> 2) == 0) {
                    int col = n0 + wn * 32 + nt * 8 + (lane & 3) * 2 + v;
                    atomicAdd((float*)Cv + col, s);
                }
            }
        }
    }
}

// ---------------- incremental top-32 (per-thread local maxima) ----------------
__global__ void topk_kernel(const float* __restrict__ f2b,
                            float* __restrict__ cval, int* __restrict__ cidx) {
    __shared__ float sv[NN];
    __shared__ unsigned long long lmax[256];
    __shared__ unsigned long long red[8];
    int head = blockIdx.x;
    int tid = threadIdx.x, lane = tid & 31, warp = tid >> 5;
    const float* f2 = f2b + (size_t)head * NN;
#pragma unroll
    for (int k = 0; k < NN / 256; k++) sv[tid + k * 256] = f2[tid + k * 256];
    __syncthreads();
    // per-thread local max over strided 32 elements
    unsigned long long best = 0;
#pragma unroll
    for (int k = 0; k < NN / 256; k++) {
        int j = tid + k * 256;
        unsigned int u = __float_as_uint(sv[j]);
        u = (u & 0x80000000u) ? ~u : (u | 0x80000000u);
        unsigned long long pk = ((unsigned long long)u << 32) | (unsigned)j;
        best = best > pk ? best : pk;
    }
    lmax[tid] = best;
    __syncthreads();
    for (int t = 0; t < 32; t++) {
        unsigned long long b = lmax[tid];
#pragma unroll
        for (int o = 16; o > 0; o >>= 1) {
            unsigned long long other = __shfl_xor_sync(0xffffffffu, b, o);
            b = b > other ? b : other;
        }
        if (lane == 0) red[warp] = b;
        __syncthreads();
        unsigned long long mx = red[0];
#pragma unroll
        for (int w = 1; w < 8; w++) mx = mx > red[w] ? mx : red[w];
        int idx = (int)(mx & 0xffffffffu);
        if (tid == 0) { cval[head * 32 + t] = sv[idx]; cidx[head * 32 + t] = idx; }
        if ((idx & 255) == tid) {   // owner removes and recomputes its local max
            sv[idx] = -INFINITY;
            unsigned long long nb = 0;
#pragma unroll
            for (int k = 0; k < NN / 256; k++) {
                int j = tid + k * 256;
                unsigned int u = __float_as_uint(sv[j]);
                u = (u & 0x80000000u) ? ~u : (u | 0x80000000u);
                unsigned long long pk = ((unsigned long long)u << 32) | (unsigned)j;
                nb = nb > pk ? nb : pk;
            }
            lmax[tid] = nb;
        }
        __syncthreads();
    }
}

__global__ void rowmax_fast(const unsigned int* __restrict__ bits,
                            const float* __restrict__ f1b,
                            const float* __restrict__ f2b,
                            const float* __restrict__ cval,
                            const int* __restrict__ cidx,
                            float* __restrict__ mb) {
    int head = blockIdx.y;
    int i = blockIdx.x * 256 + threadIdx.x;
    __shared__ float scv[32];
    __shared__ int sci[32];
    if (threadIdx.x < 32) {
        scv[threadIdx.x] = cval[head * 32 + threadIdx.x];
        sci[threadIdx.x] = cidx[head * 32 + threadIdx.x];
    }
    __syncthreads();
    const unsigned int* rb = bits + (size_t)i * WORDS;
    float mx = 0.f;
    bool found = false;
    for (int c = 0; c < 32; c++) {
        int j = sci[c];
        if ((rb[j >> 5] >> (j & 31)) & 1u) { mx = scv[c]; found = true; break; }
    }
    if (!found) {
        const float* f2 = f2b + (size_t)head * NN;
        mx = -INFINITY;
        for (int w = 0; w < WORDS; w++) {
            unsigned int b = rb[w];
            while (b) {
                int bit = __ffs(b) - 1; b &= b - 1;
                mx = fmaxf(mx, f2[w * 32 + bit]);
            }
        }
    }
    float v = f1b[(size_t)head * NN + i] + mx;
    mb[(size_t)head * NN + i] = v > 0.f ? v : 0.2f * v;
}

// single-buffer fp32-accum attention (round-13 proven)
__global__ __launch_bounds__(256) void att_hmma(
    const unsigned int* __restrict__ bits,
    const float* __restrict__ f1b, const float* __restrict__ f2b,
    const float* __restrict__ mb,
    const __half* __restrict__ Vt,
    int mode, __half* __restrict__ outH, size_t hPlane,
    float* __restrict__ numF, float* __restrict__ lout) {
    extern __shared__ __half dsm[];
    __half* Ps = dsm;
    __half* Vs = dsm + MT * PITCH;
    __shared__ float sm_l[MT];

    int head = blockIdx.y;
    int split = blockIdx.z;
    int jbase = mode ? split * (NN / 2) : 0;
    int nch = mode ? (NN / 2) / CK : NN / CK;
    const float* f1 = f1b + (size_t)head * NN;
    const float* f2 = f2b + (size_t)head * NN;
    const float* mrv = mb + (size_t)head * NN;
    int i0 = blockIdx.x * MT;

    int tid = threadIdx.x;
    int lane = tid & 31, warp = tid >> 5;
    uint32_t sb = smem_u32(dsm);

    int r = tid >> 2, q = tid & 3;
    float f1r = f1[i0 + r];
    float mr = mrv[i0 + r];
    __half2* prow = (__half2*)(Ps + r * PITCH + q * 32);

    int vn = tid >> 1, vp = tid & 1;
    const __half* vrow = Vt + (size_t)head * D * NN + (size_t)vn * NN + jbase + vp * 64;
    __half* vsrow = Vs + vn * PITCH + vp * 64;

    int mrow0 = (warp >> 1) * 16, ncol0 = (warp & 1) * 64;
    int g = lane >> 3, wl = lane & 7;
    uint32_t aaddr = sb + (mrow0 + wl + (g & 1) * 8) * (PITCH * 2) + (g >> 1) * 16;
    uint32_t baddr = sb + MT * (PITCH * 2)
                   + (ncol0 + wl + (g >> 1) * 8) * (PITCH * 2) + (g & 1) * 16;

    float acc[8][4];
#pragma unroll
    for (int nt = 0; nt < 8; nt++)
#pragma unroll
        for (int c = 0; c < 4; c++) acc[nt][c] = 0.f;
    float lsum = 0.f;

    for (int ch = 0; ch < nch; ch++) {
        int j0 = ch * CK;
        const uint4* vg = (const uint4*)(vrow + j0);
#pragma unroll
        for (int i = 0; i < 8; i++) {
            int ii = (i + 4 * vp) & 7;
            *(uint4*)(vsrow + ii * 8) = vg[ii];
        }

        unsigned int w = bits[(size_t)(i0 + r) * WORDS + ((jbase + j0) >> 5) + q];
        const float* f2c = f2 + jbase + j0 + q * 32;
#pragma unroll
        for (int s = 0; s < 16; s++) {
            int u = (s + 5 * q) & 15;
            float2 ff = *(const float2*)(f2c + 2 * u);
            float e0 = f1r + ff.x;
            float e1 = f1r + ff.y;
            e0 = fmaxf(e0, 0.2f * e0) - mr;
            e1 = fmaxf(e1, 0.2f * e1) - mr;
            float p0 = ((w >> (2 * u)) & 1u) ? __expf(e0) : 0.f;
            float p1 = ((w >> (2 * u + 1)) & 1u) ? __expf(e1) : 0.f;
            lsum += p0 + p1;
            prow[u] = __floats2half2_rn(p0, p1);
        }
        __syncthreads();

#pragma unroll
        for (int k = 0; k < 8; k++) {
            uint32_t a[4];
            ldsm4(a[0], a[1], a[2], a[3], aaddr + k * 32);
#pragma unroll
            for (int ng = 0; ng < 4; ng++) {
                uint32_t b[4];
                ldsm4(b[0], b[1], b[2], b[3], baddr + ng * (16 * PITCH * 2) + k * 32);
                mma16816(acc[2 * ng], a, b[0], b[1]);
                mma16816(acc[2 * ng + 1], a, b[2], b[3]);
            }
        }
        __syncthreads();
    }

    lsum += __shfl_xor_sync(0xffffffffu, lsum, 1);
    lsum += __shfl_xor_sync(0xffffffffu, lsum, 2);

    if (mode) {
        if (q == 0) lout[(size_t)split * NN + i0 + r] = lsum;
        float* nrow = numF + ((size_t)split * NN + i0) * D;
        int r0 = mrow0 + (lane >> 2);
#pragma unroll
        for (int nt = 0; nt < 8; nt++) {
            int col = ncol0 + nt * 8 + (lane & 3) * 2;
            *(float2*)(nrow + (size_t)r0 * D + col) = make_float2(acc[nt][0], acc[nt][1]);
            *(float2*)(nrow + (size_t)(r0 + 8) * D + col) = make_float2(acc[nt][2], acc[nt][3]);
        }
        return;
    }

    if (q == 0) sm_l[r] = lsum;
    __syncthreads();

    int r0 = mrow0 + (lane >> 2);
    float inv0 = 1.f / sm_l[r0];
    float inv1 = 1.f / sm_l[r0 + 8];
    int offH = head * 128;
#pragma unroll
    for (int nt = 0; nt < 8; nt++) {
        int col = ncol0 + nt * 8 + (lane & 3) * 2;
        float o00 = acc[nt][0] * inv0, o01 = acc[nt][1] * inv0;
        float o10 = acc[nt][2] * inv1, o11 = acc[nt][3] * inv1;
        o00 = o00 > 0.f ? o00 : expm1f(o00);
        o01 = o01 > 0.f ? o01 : expm1f(o01);
        o10 = o10 > 0.f ? o10 : expm1f(o10);
        o11 = o11 > 0.f ? o11 : expm1f(o11);
        __half h0 = __float2half_rn(o00), h1 = __float2half_rn(o01);
        __half h2 = __float2half_rn(o10), h3 = __float2half_rn(o11);
        __half2 hi0; hi0.x = h0; hi0.y = h1;
        __half2 hi1; hi1.x = h2; hi1.y = h3;
        __half2 lo0; lo0.x = __float2half_rn(o00 - __half2float(h0));
                     lo0.y = __float2half_rn(o01 - __half2float(h1));
        __half2 lo1; lo1.x = __float2half_rn(o10 - __half2float(h2));
                     lo1.y = __float2half_rn(o11 - __half2float(h3));
        size_t b0 = (size_t)(i0 + r0) * 256 + offH + col;
        size_t b1 = (size_t)(i0 + r0 + 8) * 256 + offH + col;
        *(__half2*)(outH + b0) = hi0;
        *(__half2*)(outH + b1) = hi1;
        *(__half2*)(outH + hPlane + b0) = lo0;
        *(__half2*)(outH + hPlane + b1) = lo1;
    }
}

__global__ void combine2(const float* __restrict__ num, const float* __restrict__ lpart,
                         float* __restrict__ out, __half* __restrict__ comb16) {
    int i = blockIdx.x, t = threadIdx.x;
    float s = num[(size_t)i * D + t] + num[((size_t)NN + i) * D + t];
    float l = lpart[i] + lpart[NN + i];
    float o = s / l;
    o = o > 0.f ? o : expm1f(o);
    out[(size_t)i * D + t] = o;
    __half h = __float2half_rn(o);
    comb16[(size_t)i * 256 + 128 + t] = h;
    comb16[(size_t)NN * 256 + (size_t)i * 256 + 128 + t] =
        __float2half_rn(o - __half2float(h));
}

__global__ void mean_final(const float* __restrict__ part, float* __restrict__ out) {
    int t = threadIdx.x;
    out[t] = part[t] * (1.0f / (float)NN);
}

extern "C" void kernel_launch(void* const* d_in, const int* in_sizes, int n_in,
                              void* d_out, int out_size) {
    const int* adj = (const int*)d_in[0];
    const float* x = (const float*)d_in[1];
    const float* W_heads = (const float*)d_in[2];
    const float* a_heads = (const float*)d_in[3];
    const float* W_out = (const float*)d_in[4];
    const float* a_out = (const float*)d_in[5];
    const float* ge_w1 = (const float*)d_in[6];
    const float* ge_b1 = (const float*)d_in[7];
    const float* ge_w2 = (const float*)d_in[8];
    const float* ge_b2 = (const float*)d_in[9];
    float* out = (float*)d_out;

    unsigned int* bits; cudaGetSymbolAddress((void**)&bits, g_bits);
    __half* Vt16; cudaGetSymbolAddress((void**)&Vt16, g_Vt16);
    float* f1;    cudaGetSymbolAddress((void**)&f1, g_f1);
    float* f2;    cudaGetSymbolAddress((void**)&f2, g_f2);
    float* m;     cudaGetSymbolAddress((void**)&m, g_m);
    float* f1o;   cudaGetSymbolAddress((void**)&f1o, g_f1o);
    float* f2o;   cudaGetSymbolAddress((void**)&f2o, g_f2o);
    float* mo;    cudaGetSymbolAddress((void**)&mo, g_mo);
    float* num;   cudaGetSymbolAddress((void**)&num, g_num);
    float* lpart; cudaGetSymbolAddress((void**)&lpart, g_l);
    float* part;  cudaGetSymbolAddress((void**)&part, g_part);
    __half* x16;    cudaGetSymbolAddress((void**)&x16, g_x16);
    __half* h16;    cudaGetSymbolAddress((void**)&h16, g_h16);
    __half* comb16; cudaGetSymbolAddress((void**)&comb16, g_comb16);
    __half* mlp116; cudaGetSymbolAddress((void**)&mlp116, g_mlp116);
    __half* wh16;   cudaGetSymbolAddress((void**)&wh16, g_wh16);
    __half* wo16;   cudaGetSymbolAddress((void**)&wo16, g_wo16);
    __half* w116;   cudaGetSymbolAddress((void**)&w116, g_w116);
    __half* w216;   cudaGetSymbolAddress((void**)&w216, g_w216);
    float* cval;  cudaGetSymbolAddress((void**)&cval, g_cval);
    int* cidx;    cudaGetSymbolAddress((void**)&cidx, g_cidx);

    cudaFuncSetAttribute(att_hmma, cudaFuncAttributeMaxDynamicSharedMemorySize, ATT_SMEM);

    pack_kernel<<<NN * NN / 4 / 256, 256>>>((const int4*)adj, bits);
    split_kernel<<<NN * D / 4 / 256, 256>>>(x, x16, (size_t)NN * D);
    xcomb_kernel<<<NN * D / 4 / 256, 256>>>(x, comb16);
    wprep_kernel<<<dim3(4, 4, 2), 256>>>(W_heads, D, D, wh16, D * D, D * D, 2 * D * D);
    wprep_kernel<<<dim3(8, 4, 1), 256>>>(W_out, D, 256, wo16, 256 * D, 0, 0);
    wprep_kernel<<<dim3(8, 8, 1), 256>>>(ge_w1, 256, 256, w116, 256 * 256, 0, 0);
    wprep_kernel<<<dim3(8, 4, 1), 256>>>(ge_w2, D, 256, w216, 256 * D, 0, 0);

    cudaMemsetAsync(f1, 0, 2 * NN * sizeof(float));
    cudaMemsetAsync(f2, 0, 2 * NN * sizeof(float));
    cudaMemsetAsync(f1o, 0, NN * sizeof(float));
    cudaMemsetAsync(f2o, 0, NN * sizeof(float));
    cudaMemsetAsync(part, 0, D * sizeof(float));

    hgemm16_kernel<<<dim3(NN / 128, D / 64, 2), 256>>>(
        x16, (size_t)NN * D, 0, wh16, D * D, 2 * D * D, nullptr,
        Vt16, NN, (size_t)D * NN, D, 0, 2, 0, a_heads, f1, f2);

    topk_kernel<<<2, 256>>>(f2, cval, cidx);
    rowmax_fast<<<dim3(NN / 256, 2), 256>>>(bits, f1, f2, cval, cidx, m);

    att_hmma<<<dim3(NN / MT, 2, 1), 256, ATT_SMEM>>>(
        bits, f1, f2, m, Vt16, 0, h16, (size_t)NN * 256, nullptr, nullptr);

    hgemm16_kernel<<<dim3(NN / 128, D / 64, 1), 256>>>(
        h16, (size_t)NN * 256, 0, wo16, 256 * D, 0, nullptr,
        Vt16, NN, 0, 256, 0, 2, 0, a_out, f1o, f2o);
    topk_kernel<<<1, 256>>>(f2o, cval + 64, cidx + 64);
    rowmax_fast<<<dim3(NN / 256, 1), 256>>>(bits, f1o, f2o, cval + 64, cidx + 64, mo);
    att_hmma<<<dim3(NN / MT, 1, 2), 256, ATT_SMEM>>>(
        bits, f1o, f2o, mo, Vt16, 1, nullptr, 0, num, lpart);
    combine2<<<NN, 128>>>(num, lpart, out, comb16);

    hgemm16_kernel<<<dim3(NN / 128, 256 / 64, 1), 256>>>(
        comb16, (size_t)NN * 256, 0, w116, 256 * 256, 0, ge_b1,
        mlp116, 256, 0, 256, 1, 1, (size_t)NN * 256, nullptr, f1o, f2o);
    hgemm16_kernel<<<dim3(NN / 128, D / 64, 1), 256>>>(
        mlp116, (size_t)NN * 256, 0, w216, 256 * D, 0, ge_b2,
        part, D, 0, 256, 1, 3, 0, nullptr, f1o, f2o);
    mean_final<<<1, 128>>>(part, out + (size_t)NN * D);
}